// round 11
// baseline (speedup 1.0000x reference)
#include <cuda_runtime.h>
#include <cstdint>

// EConv: out[dst] += x[src] * edge_attr[e]  over 1M edges, d=64
// Edge-order, vectorized red.global.add.v4.f32, 32-bit offsets, block=256,
// EPT=4 (best measured schedule). Output zeroing is FUSED into the main
// kernel: first 148 blocks (one per SM, wave-1 resident) zero the output,
// all blocks overlap their front-batched loads with the zero phase, then
// gate the REDs on a release/acquire flag.
// d_in[0]: x          float32 [100000*64]
// d_in[1]: edge_index int32   [2*1000000]  (row 0 = dst, row 1 = src)
// d_in[2]: edge_attr  float32 [1000000*64]
// d_out:   float32 [100000*64]

#define ROW_BYTES 256u   // 64 floats
#define EPT 4            // edges per thread
#define NZERO 148        // zeroing blocks (= SM count; all wave-1 resident)
#define OUT_F4 (100000 * 16)  // output size in float4

__device__ unsigned g_flag;   // reset to 0 each launch via memset node

__global__ __launch_bounds__(256) void econv_kernel(
    const char* __restrict__ x_b,         // x base (bytes)
    const int* __restrict__ dst_idx,      // [E]
    const int* __restrict__ src_idx,      // [E]
    const char* __restrict__ attr_b,      // edge_attr base (bytes)
    char* __restrict__ out_b,             // out base (bytes)
    int E)
{
    // ---- Phase A: first NZERO blocks zero the output ----
    if (blockIdx.x < NZERO) {
        float4* o4 = (float4*)out_b;
        float4 z = make_float4(0.f, 0.f, 0.f, 0.f);
        for (int i = blockIdx.x * 256 + threadIdx.x; i < OUT_F4; i += NZERO * 256)
            o4[i] = z;
        __threadfence();           // release: zeros visible before flag bump
        __syncthreads();
        if (threadIdx.x == 0) atomicAdd(&g_flag, 1u);
    }

    // ---- Phase B: every block front-batches its loads (overlaps Phase A) ----
    int t = blockIdx.x * blockDim.x + threadIdx.x;
    int g = t >> 4;               // edge-group id
    unsigned cb = (t & 15) * 16u; // byte offset of this thread's float4 chunk
    int e0 = g * EPT;
    bool active = (e0 < E);

    int src[EPT], dst[EPT];
    float4 xv[EPT], av[EPT];
    if (active) {
        int4 s4 = __ldcs((const int4*)(src_idx + e0));
        int4 d4 = __ldcs((const int4*)(dst_idx + e0));
        src[0] = s4.x; src[1] = s4.y; src[2] = s4.z; src[3] = s4.w;
        dst[0] = d4.x; dst[1] = d4.y; dst[2] = d4.z; dst[3] = d4.w;
        unsigned ab = (unsigned)e0 * ROW_BYTES + cb;
#pragma unroll
        for (int i = 0; i < EPT; i++) {
            xv[i] = __ldg((const float4*)(x_b + ((unsigned)src[i] * ROW_BYTES + cb)));
            av[i] = __ldcs((const float4*)(attr_b + ab + (unsigned)i * ROW_BYTES));
        }
    }

    // ---- Gate: wait until all zeroing blocks have signalled ----
    if (threadIdx.x == 0) {
        unsigned v;
        do {
            asm volatile("ld.global.acquire.gpu.u32 %0, [%1];"
                         : "=r"(v) : "l"(&g_flag));
            if (v < NZERO) __nanosleep(64);
        } while (v < NZERO);
    }
    __syncthreads();

    // ---- Phase C: multiply + vector reductions ----
    if (active) {
#pragma unroll
        for (int i = 0; i < EPT; i++) {
            av[i].x *= xv[i].x;
            av[i].y *= xv[i].y;
            av[i].z *= xv[i].z;
            av[i].w *= xv[i].w;
            char* p = out_b + ((unsigned)dst[i] * ROW_BYTES + cb);
            asm volatile(
                "red.global.add.v4.f32 [%0], {%1, %2, %3, %4};"
                :: "l"(p), "f"(av[i].x), "f"(av[i].y), "f"(av[i].z), "f"(av[i].w)
                : "memory");
        }
    }
}

extern "C" void kernel_launch(void* const* d_in, const int* in_sizes, int n_in,
                              void* d_out, int out_size) {
    const char* x_b = (const char*)d_in[0];
    const int* edge_index = (const int*)d_in[1];
    const char* attr_b = (const char*)d_in[2];

    int E = in_sizes[1] / 2;                 // 1,000,000
    const int* dst_idx = edge_index;         // row 0
    const int* src_idx = edge_index + E;     // row 1

    // Reset the completion flag (4-byte memset node, graph-capturable)
    void* flag_ptr = nullptr;
    cudaGetSymbolAddress(&flag_ptr, g_flag);
    cudaMemsetAsync(flag_ptr, 0, sizeof(unsigned));

    long long total = (long long)(E / EPT) * 16;  // 4M threads
    int blocks = (int)((total + 255) / 256);      // 15625 >= NZERO
    econv_kernel<<<blocks, 256>>>(
        x_b, dst_idx, src_idx, attr_b, (char*)d_out, E);
}

// round 12
// speedup vs baseline: 1.0791x; 1.0791x over previous
#include <cuda_runtime.h>
#include <cstdint>

// EConv: out[dst] += x[src] * edge_attr[e]  over 1M edges, d=64
// R9 schedule (EPT=4, block 256, 32-bit byte offsets, red.global.add.v4.f32)
// + PDL: the main kernel overlaps its front-batched loads with the zero
// kernel, then cudaGridDependencySynchronize() gates the REDs.
// d_in[0]: x          float32 [100000*64]
// d_in[1]: edge_index int32   [2*1000000]  (row 0 = dst, row 1 = src)
// d_in[2]: edge_attr  float32 [1000000*64]
// d_out:   float32 [100000*64]

#define ROW_BYTES 256u   // 64 floats
#define EPT 4            // edges per thread

__global__ __launch_bounds__(256) void zero_kernel(float4* __restrict__ out, int n4) {
    int i = blockIdx.x * blockDim.x + threadIdx.x;
    if (i < n4) out[i] = make_float4(0.f, 0.f, 0.f, 0.f);
}

__global__ __launch_bounds__(256) void econv_kernel(
    const char* __restrict__ x_b,         // x base (bytes)
    const int* __restrict__ dst_idx,      // [E]
    const int* __restrict__ src_idx,      // [E]
    const char* __restrict__ attr_b,      // edge_attr base (bytes)
    char* __restrict__ out_b,             // out base (bytes)
    int E)
{
    int t = blockIdx.x * blockDim.x + threadIdx.x;
    int g = t >> 4;               // edge-group id
    unsigned cb = (t & 15) * 16u; // byte offset of this thread's float4 chunk
    int e0 = g * EPT;
    if (e0 >= E) {
        cudaGridDependencySynchronize();
        return;
    }

    // Front-batch all loads — these overlap the still-running zero kernel.
    int4 s4 = __ldcs((const int4*)(src_idx + e0));
    int4 d4 = __ldcs((const int4*)(dst_idx + e0));
    int src[EPT] = {s4.x, s4.y, s4.z, s4.w};
    int dst[EPT] = {d4.x, d4.y, d4.z, d4.w};

    float4 xv[EPT], av[EPT];
    unsigned ab = (unsigned)e0 * ROW_BYTES + cb;
#pragma unroll
    for (int i = 0; i < EPT; i++) {
        xv[i] = __ldg((const float4*)(x_b + ((unsigned)src[i] * ROW_BYTES + cb)));
        av[i] = __ldcs((const float4*)(attr_b + ab + (unsigned)i * ROW_BYTES));
    }

    // Gate on the zero kernel's completion (HW grid dependency, cheap).
    cudaGridDependencySynchronize();

#pragma unroll
    for (int i = 0; i < EPT; i++) {
        av[i].x *= xv[i].x;
        av[i].y *= xv[i].y;
        av[i].z *= xv[i].z;
        av[i].w *= xv[i].w;
        char* p = out_b + ((unsigned)dst[i] * ROW_BYTES + cb);
        asm volatile(
            "red.global.add.v4.f32 [%0], {%1, %2, %3, %4};"
            :: "l"(p), "f"(av[i].x), "f"(av[i].y), "f"(av[i].z), "f"(av[i].w)
            : "memory");
    }
}

extern "C" void kernel_launch(void* const* d_in, const int* in_sizes, int n_in,
                              void* d_out, int out_size) {
    const char* x_b = (const char*)d_in[0];
    const int* edge_index = (const int*)d_in[1];
    const char* attr_b = (const char*)d_in[2];

    int E = in_sizes[1] / 2;                 // 1,000,000
    const int* dst_idx = edge_index;         // row 0
    const int* src_idx = edge_index + E;     // row 1

    // Zero pass (primary kernel of the PDL pair)
    int n4 = out_size / 4;
    zero_kernel<<<(n4 + 255) / 256, 256>>>((float4*)d_out, n4);

    // Main pass, launched with programmatic stream serialization so its
    // blocks start while zero_kernel is still draining.
    long long total = (long long)(E / EPT) * 16;  // 4M threads
    int blocks = (int)((total + 255) / 256);

    cudaLaunchConfig_t cfg = {};
    cfg.gridDim = dim3((unsigned)blocks, 1, 1);
    cfg.blockDim = dim3(256, 1, 1);
    cfg.dynamicSmemBytes = 0;
    cfg.stream = 0;
    cudaLaunchAttribute attr[1];
    attr[0].id = cudaLaunchAttributeProgrammaticStreamSerialization;
    attr[0].val.programmaticStreamSerializationAllowed = 1;
    cfg.attrs = attr;
    cfg.numAttrs = 1;

    cudaLaunchKernelEx(&cfg, econv_kernel,
                       x_b, dst_idx, src_idx, attr_b, (char*)d_out, E);
}

// round 13
// speedup vs baseline: 1.0807x; 1.0014x over previous
#include <cuda_runtime.h>
#include <cstdint>

// EConv: out[dst] += x[src] * edge_attr[e]  over 1M edges, d=64
// R9 schedule (EPT=4, block 256, 32-bit byte offsets, red.global.add.v4.f32)
// + PDL with a 148-block grid-stride zero kernel so the secondary's blocks
// co-reside and overlap their front-batched loads with the zeroing.
// d_in[0]: x          float32 [100000*64]
// d_in[1]: edge_index int32   [2*1000000]  (row 0 = dst, row 1 = src)
// d_in[2]: edge_attr  float32 [1000000*64]
// d_out:   float32 [100000*64]

#define ROW_BYTES 256u   // 64 floats
#define EPT 4            // edges per thread
#define NZB 148          // zero-kernel blocks: one per SM

__global__ __launch_bounds__(256) void zero_kernel(float4* __restrict__ out, int n4) {
    // grid-stride, one block per SM; ~27 iterations each, fully coalesced
    for (int i = blockIdx.x * 256 + threadIdx.x; i < n4; i += NZB * 256)
        out[i] = make_float4(0.f, 0.f, 0.f, 0.f);
    // allow the dependent grid to launch as early as possible
    cudaTriggerProgrammaticLaunchCompletion();
}

__global__ __launch_bounds__(256) void econv_kernel(
    const char* __restrict__ x_b,         // x base (bytes)
    const int* __restrict__ dst_idx,      // [E]
    const int* __restrict__ src_idx,      // [E]
    const char* __restrict__ attr_b,      // edge_attr base (bytes)
    char* __restrict__ out_b,             // out base (bytes)
    int E)
{
    int t = blockIdx.x * blockDim.x + threadIdx.x;
    int g = t >> 4;               // edge-group id
    unsigned cb = (t & 15) * 16u; // byte offset of this thread's float4 chunk
    int e0 = g * EPT;
    if (e0 >= E) {
        cudaGridDependencySynchronize();
        return;
    }

    // Front-batch all loads — these overlap the still-running zero kernel.
    int4 s4 = __ldcs((const int4*)(src_idx + e0));
    int4 d4 = __ldcs((const int4*)(dst_idx + e0));
    int src[EPT] = {s4.x, s4.y, s4.z, s4.w};
    int dst[EPT] = {d4.x, d4.y, d4.z, d4.w};

    float4 xv[EPT], av[EPT];
    unsigned ab = (unsigned)e0 * ROW_BYTES + cb;
#pragma unroll
    for (int i = 0; i < EPT; i++) {
        xv[i] = __ldg((const float4*)(x_b + ((unsigned)src[i] * ROW_BYTES + cb)));
        av[i] = __ldcs((const float4*)(attr_b + ab + (unsigned)i * ROW_BYTES));
    }

    // Gate on zero-kernel completion (HW grid dependency).
    cudaGridDependencySynchronize();

#pragma unroll
    for (int i = 0; i < EPT; i++) {
        av[i].x *= xv[i].x;
        av[i].y *= xv[i].y;
        av[i].z *= xv[i].z;
        av[i].w *= xv[i].w;
        char* p = out_b + ((unsigned)dst[i] * ROW_BYTES + cb);
        asm volatile(
            "red.global.add.v4.f32 [%0], {%1, %2, %3, %4};"
            :: "l"(p), "f"(av[i].x), "f"(av[i].y), "f"(av[i].z), "f"(av[i].w)
            : "memory");
    }
}

extern "C" void kernel_launch(void* const* d_in, const int* in_sizes, int n_in,
                              void* d_out, int out_size) {
    const char* x_b = (const char*)d_in[0];
    const int* edge_index = (const int*)d_in[1];
    const char* attr_b = (const char*)d_in[2];

    int E = in_sizes[1] / 2;                 // 1,000,000
    const int* dst_idx = edge_index;         // row 0
    const int* src_idx = edge_index + E;     // row 1

    // Zero pass: 148 blocks (one per SM) so the PDL secondary can co-reside.
    int n4 = out_size / 4;
    zero_kernel<<<NZB, 256>>>((float4*)d_out, n4);

    long long total = (long long)(E / EPT) * 16;  // 4M threads
    int blocks = (int)((total + 255) / 256);

    cudaLaunchConfig_t cfg = {};
    cfg.gridDim = dim3((unsigned)blocks, 1, 1);
    cfg.blockDim = dim3(256, 1, 1);
    cfg.dynamicSmemBytes = 0;
    cfg.stream = 0;
    cudaLaunchAttribute attr[1];
    attr[0].id = cudaLaunchAttributeProgrammaticStreamSerialization;
    attr[0].val.programmaticStreamSerializationAllowed = 1;
    cfg.attrs = attr;
    cfg.numAttrs = 1;

    cudaLaunchKernelEx(&cfg, econv_kernel,
                       x_b, dst_idx, src_idx, attr_b, (char*)d_out, E);
}

// round 14
// speedup vs baseline: 1.0849x; 1.0039x over previous
#include <cuda_runtime.h>
#include <cstdint>

// EConv: out[dst] += x[src] * edge_attr[e]  over 1M edges, d=64
// FINAL: edge-order processing, vectorized red.global.add.v4.f32, 32-bit
// byte-offset addressing, EPT=4, block=256. Main kernel runs at the
// measured-practical LTS chip cap (~12.3 TB/s over 776 MB compulsory L2
// traffic = ~63 us); output zeroing via memset node (~2 us, true dependency).
// d_in[0]: x          float32 [100000*64]
// d_in[1]: edge_index int32   [2*1000000]  (row 0 = dst, row 1 = src)
// d_in[2]: edge_attr  float32 [1000000*64]
// d_out:   float32 [100000*64]

#define ROW_BYTES 256u   // 64 floats
#define EPT 4            // edges per thread

__global__ __launch_bounds__(256) void econv_kernel(
    const char* __restrict__ x_b,         // x base (bytes)
    const int* __restrict__ dst_idx,      // [E]
    const int* __restrict__ src_idx,      // [E]
    const char* __restrict__ attr_b,      // edge_attr base (bytes)
    char* __restrict__ out_b,             // out base (bytes)
    int E)
{
    int t = blockIdx.x * blockDim.x + threadIdx.x;
    int g = t >> 4;               // edge-group id
    unsigned cb = (t & 15) * 16u; // byte offset of this thread's float4 chunk
    int e0 = g * EPT;
    if (e0 >= E) return;

    // One LDG.128 each for 4 src + 4 dst indices (e0 is 4-aligned)
    int4 s4 = __ldcs((const int4*)(src_idx + e0));
    int4 d4 = __ldcs((const int4*)(dst_idx + e0));
    int src[EPT] = {s4.x, s4.y, s4.z, s4.w};
    int dst[EPT] = {d4.x, d4.y, d4.z, d4.w};

    // Front-batch the 8 data loads (32-bit offsets: all arrays < 4GB).
    // x: default caching (L2-resident, 25.6 MB). attr: evict-first stream.
    float4 xv[EPT], av[EPT];
    unsigned ab = (unsigned)e0 * ROW_BYTES + cb;
#pragma unroll
    for (int i = 0; i < EPT; i++) {
        xv[i] = __ldg((const float4*)(x_b + ((unsigned)src[i] * ROW_BYTES + cb)));
        av[i] = __ldcs((const float4*)(attr_b + ab + (unsigned)i * ROW_BYTES));
    }

#pragma unroll
    for (int i = 0; i < EPT; i++) {
        av[i].x *= xv[i].x;
        av[i].y *= xv[i].y;
        av[i].z *= xv[i].z;
        av[i].w *= xv[i].w;
        char* p = out_b + ((unsigned)dst[i] * ROW_BYTES + cb);
        asm volatile(
            "red.global.add.v4.f32 [%0], {%1, %2, %3, %4};"
            :: "l"(p), "f"(av[i].x), "f"(av[i].y), "f"(av[i].z), "f"(av[i].w)
            : "memory");
    }
}

extern "C" void kernel_launch(void* const* d_in, const int* in_sizes, int n_in,
                              void* d_out, int out_size) {
    const char* x_b = (const char*)d_in[0];
    const int* edge_index = (const int*)d_in[1];
    const char* attr_b = (const char*)d_in[2];

    int E = in_sizes[1] / 2;                 // 1,000,000
    const int* dst_idx = edge_index;         // row 0
    const int* src_idx = edge_index + E;     // row 1

    // Zero the output (graph-capturable memset node; required every replay)
    cudaMemsetAsync(d_out, 0, (size_t)out_size * sizeof(float));

    long long total = (long long)(E / EPT) * 16;  // 4M threads
    int blocks = (int)((total + 255) / 256);
    econv_kernel<<<blocks, 256>>>(
        x_b, dst_idx, src_idx, attr_b, (char*)d_out, E);
}